// round 1
// baseline (speedup 1.0000x reference)
#include <cuda_runtime.h>

#define BATCH 64
#define NN    1024
#define DD    64
#define KSEL  8
#define ROWS  64
#define CTILE 128
#define NT    256

// Scratch for projected q/k: [B*N, D] row-major each (16.8 MB each).
__device__ float g_Q[(size_t)BATCH * NN * DD];
__device__ float g_K[(size_t)BATCH * NN * DD];

typedef unsigned long long u64;

__device__ __forceinline__ u64 pack2(float x, float y) {
    u64 r; asm("mov.b64 %0, {%1, %2};" : "=l"(r) : "f"(x), "f"(y)); return r;
}
__device__ __forceinline__ void unpack2(u64 v, float &x, float &y) {
    asm("mov.b64 {%0, %1}, %2;" : "=f"(x), "=f"(y) : "l"(v));
}
__device__ __forceinline__ u64 ffma2(u64 a, u64 b, u64 c) {
    u64 d; asm("fma.rn.f32x2 %0, %1, %2, %3;" : "=l"(d) : "l"(a), "l"(b), "l"(c)); return d;
}

// Insert (v,j) into descending top-8 list; tie-break: lower index ranks higher
// (matches jax.lax.top_k). Macro so the arrays provably stay in registers.
#define INS_TOP(VV, JJ, TV, TI) do {                                         \
    float _v = (VV); int _j = (JJ);                                          \
    if (_v > TV[7] || (_v == TV[7] && _j < TI[7])) {                         \
        float _cv = _v; int _cj = _j;                                        \
        _Pragma("unroll")                                                    \
        for (int _k = 0; _k < 8; _k++) {                                     \
            bool _sw = (_cv > TV[_k]) || (_cv == TV[_k] && _cj < TI[_k]);    \
            float _ov = TV[_k]; int _oj = TI[_k];                            \
            if (_sw) { TV[_k] = _cv; TI[_k] = _cj; _cv = _ov; _cj = _oj; }   \
        }                                                                    \
    }                                                                        \
} while (0)

#define INS_BOT(VV, JJ, BV, BI) do {                                         \
    float _v = (VV); int _j = (JJ);                                          \
    if (_v < BV[7] || (_v == BV[7] && _j < BI[7])) {                         \
        float _cv = _v; int _cj = _j;                                        \
        _Pragma("unroll")                                                    \
        for (int _k = 0; _k < 8; _k++) {                                     \
            bool _sw = (_cv < BV[_k]) || (_cv == BV[_k] && _cj < BI[_k]);    \
            float _ov = BV[_k]; int _oj = BI[_k];                            \
            if (_sw) { BV[_k] = _cv; BI[_k] = _cj; _cv = _ov; _cj = _oj; }   \
        }                                                                    \
    }                                                                        \
} while (0)

// ---------------------------------------------------------------------------
// Kernel 1: fused q/k projection.  C[64 rows x 128 outs] = X_tile @ [Wq;Wk]^T + b
// outs 0..63 -> g_Q, 64..127 -> g_K.
// ---------------------------------------------------------------------------
__global__ void __launch_bounds__(NT, 2) proj_kernel(
    const float* __restrict__ x,
    const float* __restrict__ wq, const float* __restrict__ bq,
    const float* __restrict__ wk, const float* __restrict__ bk)
{
    extern __shared__ float sm[];
    float* sXT = sm;                 // [DD][ROWS]   (d-major, row minor)
    float* sWT = sm + DD * ROWS;     // [DD][128]
    float* sB  = sWT + DD * 128;     // [128]

    const int t = threadIdx.x;
    const int row0 = blockIdx.x * ROWS;

    // Load & transpose X tile (64 rows x 64 d)
    for (int i = t; i < ROWS * DD / 4; i += NT) {
        int r = i >> 4, d4 = (i & 15) * 4;
        float4 v = *(const float4*)&x[(size_t)(row0 + r) * DD + d4];
        sXT[(d4 + 0) * ROWS + r] = v.x;
        sXT[(d4 + 1) * ROWS + r] = v.y;
        sXT[(d4 + 2) * ROWS + r] = v.z;
        sXT[(d4 + 3) * ROWS + r] = v.w;
    }
    // Load & transpose combined weights (128 outs x 64 d)
    for (int i = t; i < 128 * DD / 4; i += NT) {
        int o = i >> 4, d4 = (i & 15) * 4;
        const float* wsrc = (o < 64) ? &wq[o * DD + d4] : &wk[(o - 64) * DD + d4];
        float4 v = *(const float4*)wsrc;
        sWT[(d4 + 0) * 128 + o] = v.x;
        sWT[(d4 + 1) * 128 + o] = v.y;
        sWT[(d4 + 2) * 128 + o] = v.z;
        sWT[(d4 + 3) * 128 + o] = v.w;
    }
    if (t < 128) sB[t] = (t < 64) ? bq[t] : bk[t - 64];
    __syncthreads();

    const int ct = t & 15, rt = t >> 4;   // 16x16 thread grid, micro 4 rows x 8 outs
    u64 acc[4][4];
    #pragma unroll
    for (int i = 0; i < 4; i++)
        #pragma unroll
        for (int j = 0; j < 4; j++) acc[i][j] = 0ull;

    #pragma unroll 8
    for (int d = 0; d < DD; d++) {
        float4 a = *(const float4*)&sXT[d * ROWS + rt * 4];
        const double2* bp = (const double2*)&sWT[d * 128 + ct * 8];
        double2 b01 = bp[0], b23 = bp[1];
        u64 bb[4] = { __double_as_longlong(b01.x), __double_as_longlong(b01.y),
                      __double_as_longlong(b23.x), __double_as_longlong(b23.y) };
        u64 ad[4] = { pack2(a.x, a.x), pack2(a.y, a.y),
                      pack2(a.z, a.z), pack2(a.w, a.w) };
        #pragma unroll
        for (int i = 0; i < 4; i++)
            #pragma unroll
            for (int j = 0; j < 4; j++)
                acc[i][j] = ffma2(ad[i], bb[j], acc[i][j]);
    }

    #pragma unroll
    for (int i = 0; i < 4; i++) {
        size_t grow = (size_t)(row0 + rt * 4 + i);
        #pragma unroll
        for (int j = 0; j < 4; j++) {
            float v0, v1; unpack2(acc[i][j], v0, v1);
            int o0 = ct * 8 + j * 2;
            float r0 = v0 + sB[o0], r1 = v1 + sB[o0 + 1];
            if (o0 < 64) {
                g_Q[grow * DD + o0]     = r0;
                g_Q[grow * DD + o0 + 1] = r1;
            } else {
                g_K[grow * DD + o0 - 64] = r0;
                g_K[grow * DD + o0 - 63] = r1;
            }
        }
    }
}

// ---------------------------------------------------------------------------
// Kernel 2: per CTA: 64 rows of one batch vs all 1024 columns.
// Raw q.k scores (tanh/scale are monotone -> skipped), running top8/bot8,
// then write mask rows (zeros + 8 ones / 8 minus-ones).
// ---------------------------------------------------------------------------
__global__ void __launch_bounds__(NT, 2) score_topk_kernel(float* __restrict__ out)
{
    extern __shared__ float sm[];
    float* sQT = sm;                      // [DD][68]   q^T tile (stride 68)
    float* sKT = sm + DD * 68;            // [DD][132]  k^T tile (stride 132)
    float* sS  = sKT + DD * 132;          // [64][132]  score staging (stride 132)

    const int t  = threadIdx.x;
    const int b  = blockIdx.x >> 4;            // 16 row-tiles per batch
    const int r0 = (blockIdx.x & 15) * ROWS;

    // Load & transpose Q tile (64 rows x 64 d)
    const float* Qg = g_Q + ((size_t)b * NN + r0) * DD;
    for (int i = t; i < ROWS * DD / 4; i += NT) {
        int r = i >> 4, d4 = (i & 15) * 4;
        float4 v = *(const float4*)&Qg[(size_t)r * DD + d4];
        sQT[(d4 + 0) * 68 + r] = v.x;
        sQT[(d4 + 1) * 68 + r] = v.y;
        sQT[(d4 + 2) * 68 + r] = v.z;
        sQT[(d4 + 3) * 68 + r] = v.w;
    }

    const float NEG_INF = __int_as_float(0xff800000);
    const float POS_INF = __int_as_float(0x7f800000);
    float tv[KSEL], bvv[KSEL];
    int   ti[KSEL], bi[KSEL];
    #pragma unroll
    for (int k = 0; k < KSEL; k++) {
        tv[k] = NEG_INF; bvv[k] = POS_INF;
        ti[k] = 0x7fffffff; bi[k] = 0x7fffffff;
    }

    const int ct = t & 15, rt = t >> 4;   // GEMM micro-tile: 4 rows x 8 cols
    const int part = t & 3, srow = t >> 2; // scan: 4 threads per row
    const float* Kg = g_K + (size_t)b * NN * DD;

    for (int tile = 0; tile < NN / CTILE; tile++) {
        __syncthreads();   // prev scan done before overwriting sKT/sS
        // Load & transpose K tile (128 cols x 64 d)
        for (int i = t; i < CTILE * DD / 4; i += NT) {
            int c = i >> 4, d4 = (i & 15) * 4;
            float4 v = *(const float4*)&Kg[(size_t)(tile * CTILE + c) * DD + d4];
            sKT[(d4 + 0) * 132 + c] = v.x;
            sKT[(d4 + 1) * 132 + c] = v.y;
            sKT[(d4 + 2) * 132 + c] = v.z;
            sKT[(d4 + 3) * 132 + c] = v.w;
        }
        __syncthreads();

        u64 acc[4][4];
        #pragma unroll
        for (int i = 0; i < 4; i++)
            #pragma unroll
            for (int j = 0; j < 4; j++) acc[i][j] = 0ull;

        #pragma unroll 8
        for (int d = 0; d < DD; d++) {
            float4 a = *(const float4*)&sQT[d * 68 + rt * 4];
            const double2* bp = (const double2*)&sKT[d * 132 + ct * 8];
            double2 b01 = bp[0], b23 = bp[1];
            u64 bb[4] = { __double_as_longlong(b01.x), __double_as_longlong(b01.y),
                          __double_as_longlong(b23.x), __double_as_longlong(b23.y) };
            u64 ad[4] = { pack2(a.x, a.x), pack2(a.y, a.y),
                          pack2(a.z, a.z), pack2(a.w, a.w) };
            #pragma unroll
            for (int i = 0; i < 4; i++)
                #pragma unroll
                for (int j = 0; j < 4; j++)
                    acc[i][j] = ffma2(ad[i], bb[j], acc[i][j]);
        }

        // Stage scores
        #pragma unroll
        for (int i = 0; i < 4; i++) {
            float v0, v1, v2, v3, v4, v5, v6, v7;
            unpack2(acc[i][0], v0, v1);
            unpack2(acc[i][1], v2, v3);
            unpack2(acc[i][2], v4, v5);
            unpack2(acc[i][3], v6, v7);
            float4 w0 = make_float4(v0, v1, v2, v3);
            float4 w1 = make_float4(v4, v5, v6, v7);
            *(float4*)&sS[(rt * 4 + i) * 132 + ct * 8]     = w0;
            *(float4*)&sS[(rt * 4 + i) * 132 + ct * 8 + 4] = w1;
        }
        __syncthreads();

        // Scan: thread (srow, part) scans 32 cols, rotated start vs bank layout
        const int jbase = tile * CTILE;
        #pragma unroll 4
        for (int it = 0; it < 32; it++) {
            int c = part * 32 + ((it + part * 8) & 31);
            float v = sS[srow * 132 + c];
            int j = jbase + c;
            INS_TOP(v, j, tv, ti);
            INS_BOT(v, j, bvv, bi);
        }
    }

    // Merge the 4 partial lists per row
    __syncthreads();
    float* cvals = sS;           // 64 rows x 64 entries
    int*   cidx  = (int*)sKT;
    {
        int base = srow * 64 + part * 16;
        #pragma unroll
        for (int k = 0; k < KSEL; k++) {
            cvals[base + k]         = tv[k];  cidx[base + k]         = ti[k];
            cvals[base + 8 + k]     = bvv[k]; cidx[base + 8 + k]     = bi[k];
        }
    }
    __syncthreads();

    if (t < ROWS) {
        #pragma unroll
        for (int k = 0; k < KSEL; k++) {
            tv[k] = NEG_INF; bvv[k] = POS_INF;
            ti[k] = 0x7fffffff; bi[k] = 0x7fffffff;
        }
        int base = t * 64;
        for (int p = 0; p < 4; p++) {
            #pragma unroll
            for (int k = 0; k < KSEL; k++) {
                float v = cvals[base + p * 16 + k];
                int   j = cidx [base + p * 16 + k];
                INS_TOP(v, j, tv, ti);
                float v2 = cvals[base + p * 16 + 8 + k];
                int   j2 = cidx [base + p * 16 + 8 + k];
                INS_BOT(v2, j2, bvv, bi);
            }
        }
    }

    // Zero-fill this CTA's output rows (affinity + penalty), then scatter.
    const size_t aoff = ((size_t)b * NN + r0) * NN;
    float* aff = out + aoff;
    float* pen = out + (size_t)BATCH * NN * NN + aoff;
    const float4 z = make_float4(0.f, 0.f, 0.f, 0.f);
    for (int i = t; i < ROWS * NN / 4; i += NT) {
        ((float4*)aff)[i] = z;
        ((float4*)pen)[i] = z;
    }
    __syncthreads();
    if (t < ROWS) {
        float* arow = aff + (size_t)t * NN;
        float* prow = pen + (size_t)t * NN;
        #pragma unroll
        for (int k = 0; k < KSEL; k++) {
            arow[ti[k]] = 1.0f;
            prow[bi[k]] = -1.0f;
        }
    }
}

// ---------------------------------------------------------------------------
extern "C" void kernel_launch(void* const* d_in, const int* in_sizes, int n_in,
                              void* d_out, int out_size)
{
    const float* x  = (const float*)d_in[0];
    const float* wq = (const float*)d_in[1];
    const float* bq = (const float*)d_in[2];
    const float* wk = (const float*)d_in[3];
    const float* bk = (const float*)d_in[4];
    float* out = (float*)d_out;

    const int proj_smem = (DD * ROWS + DD * 128 + 128) * (int)sizeof(float);       // ~48.5 KB
    const int main_smem = (DD * 68 + DD * 132 + 64 * 132) * (int)sizeof(float);    // ~83 KB

    cudaFuncSetAttribute(proj_kernel,
                         cudaFuncAttributeMaxDynamicSharedMemorySize, proj_smem);
    cudaFuncSetAttribute(score_topk_kernel,
                         cudaFuncAttributeMaxDynamicSharedMemorySize, main_smem);

    const int grid = (BATCH * NN) / ROWS;   // 1024 CTAs
    proj_kernel<<<grid, NT, proj_smem>>>(x, wq, bq, wk, bk);
    score_topk_kernel<<<grid, NT, main_smem>>>(out);
}